// round 5
// baseline (speedup 1.0000x reference)
#include <cuda_runtime.h>
#include <cstdint>
#include <math.h>

// N=8 (7 completed blocks + partial), D=2048, B*L=8192 rows.
// Persistent double-buffered pipeline: 296 CTAs (2/SM), each grid-strides
// over rows. While computing row r, cp.async prefetches row r+stride into
// the alternate smem buffer; blocks 6 & 7 are prefetched into registers.
#define NB 8
#define NSTAGE 6
#define DDIM 2048
#define THREADS 256
#define BUF_FLOATS (NSTAGE * DDIM)
#define SMEM_BYTES (2 * BUF_FLOATS * 4)   // 96 KB (two 48 KB buffers)

__device__ __forceinline__ void cp_async16(unsigned int smem_addr, const void* gptr) {
    asm volatile("cp.async.cg.shared.global [%0], [%1], 16;\n"
                 :: "r"(smem_addr), "l"(gptr));
}

__device__ __forceinline__ float4 f4zero() { return make_float4(0.f, 0.f, 0.f, 0.f); }

__global__ __launch_bounds__(THREADS, 2)
void attn_residual_kernel(const float* __restrict__ blocks,     // [7, BL, D]
                          const float* __restrict__ partial,    // [BL, D]
                          const float* __restrict__ norm_scale, // [D]
                          const float* __restrict__ proj,       // [D]
                          float* __restrict__ out,              // [BL, D]
                          int BL)
{
    extern __shared__ float sv[];        // [2][NSTAGE][DDIM]
    __shared__ float red[THREADS / 32][16];
    __shared__ float fin[16];

    const int t    = threadIdx.x;
    const int lane = t & 31;
    const int warp = t >> 5;
    const int stride = gridDim.x;

    const size_t nStride = (size_t)BL * DDIM;

    const int d0 = t * 4;            // [0, 1024)
    const int d1 = 1024 + t * 4;     // [1024, 2048)

    unsigned int svb;
    asm("{ .reg .u64 tmp; cvta.to.shared.u64 tmp, %1; cvt.u32.u64 %0, tmp; }"
        : "=r"(svb) : "l"(sv));

    // q[d] = proj[d] * norm_scale[d]
    float4 q0, q1;
    {
        float4 p = *(const float4*)(proj + d0);
        float4 s = *(const float4*)(norm_scale + d0);
        q0 = make_float4(p.x * s.x, p.y * s.y, p.z * s.z, p.w * s.w);
        p = *(const float4*)(proj + d1);
        s = *(const float4*)(norm_scale + d1);
        q1 = make_float4(p.x * s.x, p.y * s.y, p.z * s.z, p.w * s.w);
    }

    int row = blockIdx.x;
    if (row >= BL) return;

    // ---- Prologue: stage row's 6 blocks into buf0; blocks 6/7 into regs ----
    {
        const size_t rowOff = (size_t)row * DDIM;
#pragma unroll
        for (int n = 0; n < NSTAGE; n++) {
            const float* src = blocks + (size_t)n * nStride + rowOff;
            cp_async16(svb + (unsigned)(n * DDIM + d0) * 4u, src + d0);
            cp_async16(svb + (unsigned)(n * DDIM + d1) * 4u, src + d1);
        }
    }
    asm volatile("cp.async.commit_group;\n" ::: "memory");

    float4 a6c, b6c, a7c, b7c;
    {
        const size_t rowOff = (size_t)row * DDIM;
        const float* s6 = blocks + (size_t)6 * nStride + rowOff;
        const float* s7 = partial + rowOff;
        a6c = *(const float4*)(s6 + d0);  b6c = *(const float4*)(s6 + d1);
        a7c = *(const float4*)(s7 + d0);  b7c = *(const float4*)(s7 + d1);
    }

    int cur = 0;
    for (; row < BL; row += stride) {
        const int nrow = row + stride;
        const bool has_next = (nrow < BL);

        // ---- Prefetch NEXT row (keeps DRAM busy through this row's compute)
        if (has_next) {
            const size_t nOff = (size_t)nrow * DDIM;
            const unsigned bufb = svb + (unsigned)((1 - cur) * BUF_FLOATS) * 4u;
#pragma unroll
            for (int n = 0; n < NSTAGE; n++) {
                const float* src = blocks + (size_t)n * nStride + nOff;
                cp_async16(bufb + (unsigned)(n * DDIM + d0) * 4u, src + d0);
                cp_async16(bufb + (unsigned)(n * DDIM + d1) * 4u, src + d1);
            }
        }
        asm volatile("cp.async.commit_group;\n" ::: "memory");

        float4 a6n = f4zero(), b6n = f4zero(), a7n = f4zero(), b7n = f4zero();
        if (has_next) {
            const size_t nOff = (size_t)nrow * DDIM;
            const float* s6 = blocks + (size_t)6 * nStride + nOff;
            const float* s7 = partial + nOff;
            a6n = *(const float4*)(s6 + d0);  b6n = *(const float4*)(s6 + d1);
            a7n = *(const float4*)(s7 + d0);  b7n = *(const float4*)(s7 + d1);
        }

        // ---- Wait for CURRENT row's staged buffer (1 group may remain) ----
        asm volatile("cp.async.wait_group 1;\n" ::: "memory");

        const float* buf = sv + cur * BUF_FLOATS;

        // ---- Pass 1: dot & sumsq per n ----
        float dotp[NB], ssq[NB];
#pragma unroll
        for (int n = 0; n < NSTAGE; n++) {
            float4 a = *(const float4*)(buf + n * DDIM + d0);
            float4 b = *(const float4*)(buf + n * DDIM + d1);
            dotp[n] = q0.x * a.x + q0.y * a.y + q0.z * a.z + q0.w * a.w
                    + q1.x * b.x + q1.y * b.y + q1.z * b.z + q1.w * b.w;
            ssq[n]  = a.x * a.x + a.y * a.y + a.z * a.z + a.w * a.w
                    + b.x * b.x + b.y * b.y + b.z * b.z + b.w * b.w;
        }
        dotp[6] = q0.x * a6c.x + q0.y * a6c.y + q0.z * a6c.z + q0.w * a6c.w
                + q1.x * b6c.x + q1.y * b6c.y + q1.z * b6c.z + q1.w * b6c.w;
        ssq[6]  = a6c.x * a6c.x + a6c.y * a6c.y + a6c.z * a6c.z + a6c.w * a6c.w
                + b6c.x * b6c.x + b6c.y * b6c.y + b6c.z * b6c.z + b6c.w * b6c.w;
        dotp[7] = q0.x * a7c.x + q0.y * a7c.y + q0.z * a7c.z + q0.w * a7c.w
                + q1.x * b7c.x + q1.y * b7c.y + q1.z * b7c.z + q1.w * b7c.w;
        ssq[7]  = a7c.x * a7c.x + a7c.y * a7c.y + a7c.z * a7c.z + a7c.w * a7c.w
                + b7c.x * b7c.x + b7c.y * b7c.y + b7c.z * b7c.z + b7c.w * b7c.w;

        // ---- Block reduction of 16 scalars ----
#pragma unroll
        for (int n = 0; n < NB; n++) {
#pragma unroll
            for (int o = 16; o > 0; o >>= 1) {
                dotp[n] += __shfl_down_sync(0xffffffffu, dotp[n], o);
                ssq[n]  += __shfl_down_sync(0xffffffffu, ssq[n],  o);
            }
        }
        __syncthreads();   // also orders fin reads from previous iteration
        if (lane == 0) {
#pragma unroll
            for (int n = 0; n < NB; n++) {
                red[warp][n]     = dotp[n];
                red[warp][8 + n] = ssq[n];
            }
        }
        __syncthreads();
        if (t < 16) {
            float s = 0.f;
#pragma unroll
            for (int w = 0; w < THREADS / 32; w++) s += red[w][t];
            fin[t] = s;
        }
        __syncthreads();

        // ---- Softmax over n (redundant per-thread) ----
        float wgt[NB];
        float mx = -INFINITY;
#pragma unroll
        for (int n = 0; n < NB; n++) {
            float rms = sqrtf(fin[8 + n] * (1.0f / DDIM) + 1e-6f);
            wgt[n] = fin[n] / rms;
            mx = fmaxf(mx, wgt[n]);
        }
        float wsum = 0.f;
#pragma unroll
        for (int n = 0; n < NB; n++) {
            wgt[n] = __expf(wgt[n] - mx);
            wsum += wgt[n];
        }
        const float inv = 1.0f / wsum;

        // ---- Pass 2: weighted sum; store ----
        float4 o0 = f4zero(), o1 = f4zero();
#pragma unroll
        for (int n = 0; n < NSTAGE; n++) {
            float w = wgt[n] * inv;
            float4 a = *(const float4*)(buf + n * DDIM + d0);
            float4 b = *(const float4*)(buf + n * DDIM + d1);
            o0.x += w * a.x; o0.y += w * a.y; o0.z += w * a.z; o0.w += w * a.w;
            o1.x += w * b.x; o1.y += w * b.y; o1.z += w * b.z; o1.w += w * b.w;
        }
        {
            const float w6 = wgt[6] * inv, w7 = wgt[7] * inv;
            o0.x += w6 * a6c.x + w7 * a7c.x;  o0.y += w6 * a6c.y + w7 * a7c.y;
            o0.z += w6 * a6c.z + w7 * a7c.z;  o0.w += w6 * a6c.w + w7 * a7c.w;
            o1.x += w6 * b6c.x + w7 * b7c.x;  o1.y += w6 * b6c.y + w7 * b7c.y;
            o1.z += w6 * b6c.z + w7 * b7c.z;  o1.w += w6 * b6c.w + w7 * b7c.w;
        }
        const size_t rowOff = (size_t)row * DDIM;
        *(float4*)(out + rowOff + d0) = o0;
        *(float4*)(out + rowOff + d1) = o1;

        // ---- Rotate ----
        a6c = a6n; b6c = b6n; a7c = a7n; b7c = b7n;
        cur ^= 1;
    }
}

extern "C" void kernel_launch(void* const* d_in, const int* in_sizes, int n_in,
                              void* d_out, int out_size)
{
    const float* blocks     = (const float*)d_in[0];
    const float* partial    = (const float*)d_in[1];
    const float* norm_scale = (const float*)d_in[2];
    const float* proj       = (const float*)d_in[3];
    float* out              = (float*)d_out;

    const int BL = in_sizes[1] / DDIM;

    static int configured = 0;
    if (!configured) {
        cudaFuncSetAttribute(attn_residual_kernel,
                             cudaFuncAttributeMaxDynamicSharedMemorySize,
                             SMEM_BYTES);
        configured = 1;
    }

    int grid = 148 * 2;               // persistent: 2 CTAs per SM
    if (grid > BL) grid = BL;

    attn_residual_kernel<<<grid, THREADS, SMEM_BYTES>>>(blocks, partial,
                                                        norm_scale, proj,
                                                        out, BL);
}

// round 6
// speedup vs baseline: 1.1550x; 1.1550x over previous
#include <cuda_runtime.h>
#include <cstdint>
#include <math.h>

// N=8 (7 completed blocks + partial), D=2048, B*L=8192 rows.
// R3 structure (grid=BL, 3 CTAs/SM, 64KB smem stage) + per-block cp.async
// groups so pass-1 compute overlaps the remaining loads.
#define NB 8
#define DDIM 2048
#define THREADS 256
#define SMEM_BYTES (NB * DDIM * 4)   // 64 KB

__device__ __forceinline__ void cp_async16(unsigned int smem_addr, const void* gptr) {
    asm volatile("cp.async.cg.shared.global [%0], [%1], 16;\n"
                 :: "r"(smem_addr), "l"(gptr));
}

__global__ __launch_bounds__(THREADS, 3)
void attn_residual_kernel(const float* __restrict__ blocks,     // [7, BL, D]
                          const float* __restrict__ partial,    // [BL, D]
                          const float* __restrict__ norm_scale, // [D]
                          const float* __restrict__ proj,       // [D]
                          float* __restrict__ out,              // [BL, D]
                          int BL)
{
    extern __shared__ float sv[];        // [NB][DDIM]
    const int row  = blockIdx.x;
    const int t    = threadIdx.x;
    const int lane = t & 31;
    const int warp = t >> 5;

    const size_t rowOff  = (size_t)row * DDIM;
    const size_t nStride = (size_t)BL * DDIM;

    const int d0 = t * 4;            // [0, 1024)
    const int d1 = 1024 + t * 4;     // [1024, 2048)

    // ---- Stage all 8 row slices; ONE cp.async group per block ----
    unsigned int svb;
    asm("{ .reg .u64 tmp; cvta.to.shared.u64 tmp, %1; cvt.u32.u64 %0, tmp; }"
        : "=r"(svb) : "l"(sv));
#pragma unroll
    for (int n = 0; n < NB; n++) {
        const float* src = (n < NB - 1) ? (blocks + (size_t)n * nStride + rowOff)
                                        : (partial + rowOff);
        cp_async16(svb + (unsigned)(n * DDIM + d0) * 4u, src + d0);
        cp_async16(svb + (unsigned)(n * DDIM + d1) * 4u, src + d1);
        asm volatile("cp.async.commit_group;\n" ::: "memory");
    }

    // q[d] = proj[d] * norm_scale[d] (overlaps with cp.async)
    float4 q0, q1;
    {
        float4 p = *(const float4*)(proj + d0);
        float4 s = *(const float4*)(norm_scale + d0);
        q0 = make_float4(p.x * s.x, p.y * s.y, p.z * s.z, p.w * s.w);
        p = *(const float4*)(proj + d1);
        s = *(const float4*)(norm_scale + d1);
        q1 = make_float4(p.x * s.x, p.y * s.y, p.z * s.z, p.w * s.w);
    }

    // ---- Pass 1: process block n as soon as its group lands ----
    float dotp[NB], ssq[NB];
#define PROC_BLOCK(n, W)                                                     \
    do {                                                                     \
        asm volatile("cp.async.wait_group %0;\n" :: "n"(W) : "memory");      \
        float4 a = *(const float4*)(sv + (n) * DDIM + d0);                   \
        float4 b = *(const float4*)(sv + (n) * DDIM + d1);                   \
        dotp[n] = q0.x * a.x + q0.y * a.y + q0.z * a.z + q0.w * a.w          \
                + q1.x * b.x + q1.y * b.y + q1.z * b.z + q1.w * b.w;         \
        ssq[n]  = a.x * a.x + a.y * a.y + a.z * a.z + a.w * a.w              \
                + b.x * b.x + b.y * b.y + b.z * b.z + b.w * b.w;             \
    } while (0)

    PROC_BLOCK(0, 7);
    PROC_BLOCK(1, 6);
    PROC_BLOCK(2, 5);
    PROC_BLOCK(3, 4);
    PROC_BLOCK(4, 3);
    PROC_BLOCK(5, 2);
    PROC_BLOCK(6, 1);
    PROC_BLOCK(7, 0);
#undef PROC_BLOCK

    // ---- Block reduction of 16 scalars ----
    __shared__ float red[THREADS / 32][16];
    __shared__ float fin[16];
#pragma unroll
    for (int n = 0; n < NB; n++) {
#pragma unroll
        for (int o = 16; o > 0; o >>= 1) {
            dotp[n] += __shfl_down_sync(0xffffffffu, dotp[n], o);
            ssq[n]  += __shfl_down_sync(0xffffffffu, ssq[n],  o);
        }
    }
    if (lane == 0) {
#pragma unroll
        for (int n = 0; n < NB; n++) {
            red[warp][n]     = dotp[n];
            red[warp][8 + n] = ssq[n];
        }
    }
    __syncthreads();
    if (t < 16) {
        float s = 0.f;
#pragma unroll
        for (int w = 0; w < THREADS / 32; w++) s += red[w][t];
        fin[t] = s;
    }
    __syncthreads();

    // ---- Softmax over n (redundant per-thread; trivial) ----
    float wgt[NB];
    float mx = -INFINITY;
#pragma unroll
    for (int n = 0; n < NB; n++) {
        float rms = sqrtf(fin[8 + n] * (1.0f / DDIM) + 1e-6f);
        wgt[n] = fin[n] / rms;
        mx = fmaxf(mx, wgt[n]);
    }
    float wsum = 0.f;
#pragma unroll
    for (int n = 0; n < NB; n++) {
        wgt[n] = __expf(wgt[n] - mx);
        wsum += wgt[n];
    }
    const float inv = 1.0f / wsum;

    // ---- Pass 2: weighted sum from smem; streaming store (evict-first) ----
    float4 o0 = make_float4(0.f, 0.f, 0.f, 0.f);
    float4 o1 = make_float4(0.f, 0.f, 0.f, 0.f);
#pragma unroll
    for (int n = 0; n < NB; n++) {
        float w = wgt[n] * inv;
        float4 a = *(const float4*)(sv + n * DDIM + d0);
        float4 b = *(const float4*)(sv + n * DDIM + d1);
        o0.x += w * a.x; o0.y += w * a.y; o0.z += w * a.z; o0.w += w * a.w;
        o1.x += w * b.x; o1.y += w * b.y; o1.z += w * b.z; o1.w += w * b.w;
    }
    __stcs((float4*)(out + rowOff + d0), o0);
    __stcs((float4*)(out + rowOff + d1), o1);
}

extern "C" void kernel_launch(void* const* d_in, const int* in_sizes, int n_in,
                              void* d_out, int out_size)
{
    const float* blocks     = (const float*)d_in[0];
    const float* partial    = (const float*)d_in[1];
    const float* norm_scale = (const float*)d_in[2];
    const float* proj       = (const float*)d_in[3];
    float* out              = (float*)d_out;

    const int BL = in_sizes[1] / DDIM;

    static int configured = 0;
    if (!configured) {
        cudaFuncSetAttribute(attn_residual_kernel,
                             cudaFuncAttributeMaxDynamicSharedMemorySize,
                             SMEM_BYTES);
        configured = 1;
    }

    attn_residual_kernel<<<BL, THREADS, SMEM_BYTES>>>(blocks, partial,
                                                      norm_scale, proj,
                                                      out, BL);
}

// round 7
// speedup vs baseline: 1.1753x; 1.0175x over previous
#include <cuda_runtime.h>
#include <cstdint>
#include <math.h>

// N=8 (7 completed blocks + partial), D=2048, B*L=8192 rows.
// Stage-in via cp.async.bulk (TMA-style 8KB contiguous copies, 1 issuing
// thread, mbarrier complete_tx) instead of 128 per-CTA LDGSTS warp-ops.
#define NB 8
#define DDIM 2048
#define THREADS 256
#define ROW_BYTES (DDIM * 4)              // 8 KB per block slice
#define SMEM_BYTES (NB * DDIM * 4)        // 64 KB data stage

__global__ __launch_bounds__(THREADS, 3)
void attn_residual_kernel(const float* __restrict__ blocks,     // [7, BL, D]
                          const float* __restrict__ partial,    // [BL, D]
                          const float* __restrict__ norm_scale, // [D]
                          const float* __restrict__ proj,       // [D]
                          float* __restrict__ out,              // [BL, D]
                          int BL)
{
    extern __shared__ float sv[];         // [NB][DDIM], 16B aligned
    __shared__ __align__(8) unsigned long long mbar;
    __shared__ float red[THREADS / 32][16];
    __shared__ float fin[16];

    const int row  = blockIdx.x;
    const int t    = threadIdx.x;
    const int lane = t & 31;
    const int warp = t >> 5;

    const size_t rowOff  = (size_t)row * DDIM;
    const size_t nStride = (size_t)BL * DDIM;

    const int d0 = t * 4;            // [0, 1024)
    const int d1 = 1024 + t * 4;     // [1024, 2048)

    unsigned int svb, mb;
    asm("{ .reg .u64 tmp; cvta.to.shared.u64 tmp, %1; cvt.u32.u64 %0, tmp; }"
        : "=r"(svb) : "l"(sv));
    asm("{ .reg .u64 tmp; cvta.to.shared.u64 tmp, %1; cvt.u32.u64 %0, tmp; }"
        : "=r"(mb) : "l"(&mbar));

    // ---- Init mbarrier, then bulk-copy all 8 contiguous 8KB slices ----
    if (t == 0) {
        asm volatile("mbarrier.init.shared.b64 [%0], 1;" :: "r"(mb) : "memory");
    }
    __syncthreads();

    if (t == 0) {
        asm volatile("mbarrier.arrive.expect_tx.shared.b64 _, [%0], %1;"
                     :: "r"(mb), "r"(NB * ROW_BYTES) : "memory");
#pragma unroll
        for (int n = 0; n < NB; n++) {
            const float* src = (n < NB - 1)
                                 ? (blocks + (size_t)n * nStride + rowOff)
                                 : (partial + rowOff);
            asm volatile(
                "cp.async.bulk.shared::cluster.global.mbarrier::complete_tx::bytes"
                " [%0], [%1], %2, [%3];"
                :: "r"(svb + (unsigned)(n * ROW_BYTES)), "l"(src),
                   "r"(ROW_BYTES), "r"(mb)
                : "memory");
        }
    }

    // q[d] = proj[d] * norm_scale[d] (overlaps with bulk copies)
    float4 q0, q1;
    {
        float4 p = *(const float4*)(proj + d0);
        float4 s = *(const float4*)(norm_scale + d0);
        q0 = make_float4(p.x * s.x, p.y * s.y, p.z * s.z, p.w * s.w);
        p = *(const float4*)(proj + d1);
        s = *(const float4*)(norm_scale + d1);
        q1 = make_float4(p.x * s.x, p.y * s.y, p.z * s.z, p.w * s.w);
    }

    // ---- Wait for the full 64KB stage (phase 0) ----
    {
        unsigned int done;
        asm volatile(
            "{\n\t"
            ".reg .pred p;\n\t"
            "mbarrier.try_wait.parity.acquire.cta.shared::cta.b64 p, [%1], 0;\n\t"
            "selp.b32 %0, 1, 0, p;\n\t"
            "}" : "=r"(done) : "r"(mb) : "memory");
        if (!done) {
            asm volatile(
                "{\n\t"
                ".reg .pred P1;\n\t"
                "WAIT_LOOP:\n\t"
                "mbarrier.try_wait.parity.acquire.cta.shared::cta.b64 P1, [%0], 0, 0x989680;\n\t"
                "@P1 bra.uni WAIT_DONE;\n\t"
                "bra.uni WAIT_LOOP;\n\t"
                "WAIT_DONE:\n\t"
                "}" :: "r"(mb) : "memory");
        }
    }

    // ---- Pass 1: dot & sumsq per n ----
    float dotp[NB], ssq[NB];
#pragma unroll
    for (int n = 0; n < NB; n++) {
        float4 a = *(const float4*)(sv + n * DDIM + d0);
        float4 b = *(const float4*)(sv + n * DDIM + d1);
        dotp[n] = q0.x * a.x + q0.y * a.y + q0.z * a.z + q0.w * a.w
                + q1.x * b.x + q1.y * b.y + q1.z * b.z + q1.w * b.w;
        ssq[n]  = a.x * a.x + a.y * a.y + a.z * a.z + a.w * a.w
                + b.x * b.x + b.y * b.y + b.z * b.z + b.w * b.w;
    }

    // ---- Block reduction of 16 scalars ----
#pragma unroll
    for (int n = 0; n < NB; n++) {
#pragma unroll
        for (int o = 16; o > 0; o >>= 1) {
            dotp[n] += __shfl_down_sync(0xffffffffu, dotp[n], o);
            ssq[n]  += __shfl_down_sync(0xffffffffu, ssq[n],  o);
        }
    }
    if (lane == 0) {
#pragma unroll
        for (int n = 0; n < NB; n++) {
            red[warp][n]     = dotp[n];
            red[warp][8 + n] = ssq[n];
        }
    }
    __syncthreads();
    if (t < 16) {
        float s = 0.f;
#pragma unroll
        for (int w = 0; w < THREADS / 32; w++) s += red[w][t];
        fin[t] = s;
    }
    __syncthreads();

    // ---- Softmax over n (redundant per-thread; trivial) ----
    float wgt[NB];
    float mx = -INFINITY;
#pragma unroll
    for (int n = 0; n < NB; n++) {
        float rms = sqrtf(fin[8 + n] * (1.0f / DDIM) + 1e-6f);
        wgt[n] = fin[n] / rms;
        mx = fmaxf(mx, wgt[n]);
    }
    float wsum = 0.f;
#pragma unroll
    for (int n = 0; n < NB; n++) {
        wgt[n] = __expf(wgt[n] - mx);
        wsum += wgt[n];
    }
    const float inv = 1.0f / wsum;

    // ---- Pass 2: weighted sum from smem; streaming store ----
    float4 o0 = make_float4(0.f, 0.f, 0.f, 0.f);
    float4 o1 = make_float4(0.f, 0.f, 0.f, 0.f);
#pragma unroll
    for (int n = 0; n < NB; n++) {
        float w = wgt[n] * inv;
        float4 a = *(const float4*)(sv + n * DDIM + d0);
        float4 b = *(const float4*)(sv + n * DDIM + d1);
        o0.x += w * a.x; o0.y += w * a.y; o0.z += w * a.z; o0.w += w * a.w;
        o1.x += w * b.x; o1.y += w * b.y; o1.z += w * b.z; o1.w += w * b.w;
    }
    __stcs((float4*)(out + rowOff + d0), o0);
    __stcs((float4*)(out + rowOff + d1), o1);
}

extern "C" void kernel_launch(void* const* d_in, const int* in_sizes, int n_in,
                              void* d_out, int out_size)
{
    const float* blocks     = (const float*)d_in[0];
    const float* partial    = (const float*)d_in[1];
    const float* norm_scale = (const float*)d_in[2];
    const float* proj       = (const float*)d_in[3];
    float* out              = (float*)d_out;

    const int BL = in_sizes[1] / DDIM;

    static int configured = 0;
    if (!configured) {
        cudaFuncSetAttribute(attn_residual_kernel,
                             cudaFuncAttributeMaxDynamicSharedMemorySize,
                             SMEM_BYTES);
        configured = 1;
    }

    attn_residual_kernel<<<BL, THREADS, SMEM_BYTES>>>(blocks, partial,
                                                      norm_scale, proj,
                                                      out, BL);
}

// round 8
// speedup vs baseline: 1.1915x; 1.0138x over previous
#include <cuda_runtime.h>
#include <cstdint>
#include <math.h>

// N=8 (7 completed blocks + partial), D=2048, B*L=8192 rows.
// TMA bulk stage-in split into two mbarrier phases (4 slices each) so
// pass-1 + half the reduction overlap the remaining copy arrivals.
#define NB 8
#define DDIM 2048
#define THREADS 256
#define ROW_BYTES (DDIM * 4)              // 8 KB per block slice
#define SMEM_BYTES (NB * DDIM * 4)        // 64 KB data stage

__device__ __forceinline__ void mbar_wait(unsigned int mb) {
    unsigned int done;
    asm volatile(
        "{\n\t"
        ".reg .pred p;\n\t"
        "mbarrier.try_wait.parity.acquire.cta.shared::cta.b64 p, [%1], 0;\n\t"
        "selp.b32 %0, 1, 0, p;\n\t"
        "}" : "=r"(done) : "r"(mb) : "memory");
    if (!done) {
        asm volatile(
            "{\n\t"
            ".reg .pred P1;\n\t"
            "WAIT_LOOP_%=:\n\t"
            "mbarrier.try_wait.parity.acquire.cta.shared::cta.b64 P1, [%0], 0, 0x989680;\n\t"
            "@P1 bra.uni WAIT_DONE_%=;\n\t"
            "bra.uni WAIT_LOOP_%=;\n\t"
            "WAIT_DONE_%=:\n\t"
            "}" :: "r"(mb) : "memory");
    }
}

__global__ __launch_bounds__(THREADS, 3)
void attn_residual_kernel(const float* __restrict__ blocks,     // [7, BL, D]
                          const float* __restrict__ partial,    // [BL, D]
                          const float* __restrict__ norm_scale, // [D]
                          const float* __restrict__ proj,       // [D]
                          float* __restrict__ out,              // [BL, D]
                          int BL)
{
    extern __shared__ float sv[];         // [NB][DDIM], 16B aligned
    __shared__ __align__(8) unsigned long long mbar[2];
    __shared__ float red[THREADS / 32][16];
    __shared__ float fin[16];

    const int row  = blockIdx.x;
    const int t    = threadIdx.x;
    const int lane = t & 31;
    const int warp = t >> 5;

    const size_t rowOff  = (size_t)row * DDIM;
    const size_t nStride = (size_t)BL * DDIM;

    const int d0 = t * 4;            // [0, 1024)
    const int d1 = 1024 + t * 4;     // [1024, 2048)

    unsigned int svb, mb0, mb1;
    asm("{ .reg .u64 tmp; cvta.to.shared.u64 tmp, %1; cvt.u32.u64 %0, tmp; }"
        : "=r"(svb) : "l"(sv));
    asm("{ .reg .u64 tmp; cvta.to.shared.u64 tmp, %1; cvt.u32.u64 %0, tmp; }"
        : "=r"(mb0) : "l"(&mbar[0]));
    mb1 = mb0 + 8;

    // ---- Init mbarriers, then bulk-copy 8 contiguous 8KB slices ----
    if (t == 0) {
        asm volatile("mbarrier.init.shared.b64 [%0], 1;" :: "r"(mb0) : "memory");
        asm volatile("mbarrier.init.shared.b64 [%0], 1;" :: "r"(mb1) : "memory");
    }
    __syncthreads();

    if (t == 0) {
        asm volatile("mbarrier.arrive.expect_tx.shared.b64 _, [%0], %1;"
                     :: "r"(mb0), "r"(4 * ROW_BYTES) : "memory");
        asm volatile("mbarrier.arrive.expect_tx.shared.b64 _, [%0], %1;"
                     :: "r"(mb1), "r"(4 * ROW_BYTES) : "memory");
#pragma unroll
        for (int n = 0; n < NB; n++) {
            const float* src = (n < NB - 1)
                                 ? (blocks + (size_t)n * nStride + rowOff)
                                 : (partial + rowOff);
            const unsigned mb = (n < 4) ? mb0 : mb1;
            asm volatile(
                "cp.async.bulk.shared::cluster.global.mbarrier::complete_tx::bytes"
                " [%0], [%1], %2, [%3];"
                :: "r"(svb + (unsigned)(n * ROW_BYTES)), "l"(src),
                   "r"(ROW_BYTES), "r"(mb)
                : "memory");
        }
    }

    // q[d] = proj[d] * norm_scale[d] (overlaps with bulk copies)
    float4 q0, q1;
    {
        float4 p = *(const float4*)(proj + d0);
        float4 s = *(const float4*)(norm_scale + d0);
        q0 = make_float4(p.x * s.x, p.y * s.y, p.z * s.z, p.w * s.w);
        p = *(const float4*)(proj + d1);
        s = *(const float4*)(norm_scale + d1);
        q1 = make_float4(p.x * s.x, p.y * s.y, p.z * s.z, p.w * s.w);
    }

    float dotp[NB], ssq[NB];

#define PROC(n)                                                              \
    do {                                                                     \
        float4 a = *(const float4*)(sv + (n) * DDIM + d0);                   \
        float4 b = *(const float4*)(sv + (n) * DDIM + d1);                   \
        dotp[n] = q0.x * a.x + q0.y * a.y + q0.z * a.z + q0.w * a.w          \
                + q1.x * b.x + q1.y * b.y + q1.z * b.z + q1.w * b.w;         \
        ssq[n]  = a.x * a.x + a.y * a.y + a.z * a.z + a.w * a.w              \
                + b.x * b.x + b.y * b.y + b.z * b.z + b.w * b.w;             \
    } while (0)

    // ---- Phase 0: slices 0-3 (overlap with arrivals of 4-7) ----
    mbar_wait(mb0);
    PROC(0); PROC(1); PROC(2); PROC(3);
#pragma unroll
    for (int n = 0; n < 4; n++) {
#pragma unroll
        for (int o = 16; o > 0; o >>= 1) {
            dotp[n] += __shfl_down_sync(0xffffffffu, dotp[n], o);
            ssq[n]  += __shfl_down_sync(0xffffffffu, ssq[n],  o);
        }
    }

    // ---- Phase 1: slices 4-7 ----
    mbar_wait(mb1);
    PROC(4); PROC(5); PROC(6); PROC(7);
#undef PROC
#pragma unroll
    for (int n = 4; n < NB; n++) {
#pragma unroll
        for (int o = 16; o > 0; o >>= 1) {
            dotp[n] += __shfl_down_sync(0xffffffffu, dotp[n], o);
            ssq[n]  += __shfl_down_sync(0xffffffffu, ssq[n],  o);
        }
    }

    // ---- Cross-warp reduction of 16 scalars ----
    if (lane == 0) {
#pragma unroll
        for (int n = 0; n < NB; n++) {
            red[warp][n]     = dotp[n];
            red[warp][8 + n] = ssq[n];
        }
    }
    __syncthreads();
    if (t < 16) {
        float s = 0.f;
#pragma unroll
        for (int w = 0; w < THREADS / 32; w++) s += red[w][t];
        fin[t] = s;
    }
    __syncthreads();

    // ---- Softmax over n (redundant per-thread; trivial) ----
    float wgt[NB];
    float mx = -INFINITY;
#pragma unroll
    for (int n = 0; n < NB; n++) {
        float rms = sqrtf(fin[8 + n] * (1.0f / DDIM) + 1e-6f);
        wgt[n] = fin[n] / rms;
        mx = fmaxf(mx, wgt[n]);
    }
    float wsum = 0.f;
#pragma unroll
    for (int n = 0; n < NB; n++) {
        wgt[n] = __expf(wgt[n] - mx);
        wsum += wgt[n];
    }
    const float inv = 1.0f / wsum;

    // ---- Pass 2: weighted sum from smem; streaming store ----
    float4 o0 = make_float4(0.f, 0.f, 0.f, 0.f);
    float4 o1 = make_float4(0.f, 0.f, 0.f, 0.f);
#pragma unroll
    for (int n = 0; n < NB; n++) {
        float w = wgt[n] * inv;
        float4 a = *(const float4*)(sv + n * DDIM + d0);
        float4 b = *(const float4*)(sv + n * DDIM + d1);
        o0.x += w * a.x; o0.y += w * a.y; o0.z += w * a.z; o0.w += w * a.w;
        o1.x += w * b.x; o1.y += w * b.y; o1.z += w * b.z; o1.w += w * b.w;
    }
    __stcs((float4*)(out + rowOff + d0), o0);
    __stcs((float4*)(out + rowOff + d1), o1);
}

extern "C" void kernel_launch(void* const* d_in, const int* in_sizes, int n_in,
                              void* d_out, int out_size)
{
    const float* blocks     = (const float*)d_in[0];
    const float* partial    = (const float*)d_in[1];
    const float* norm_scale = (const float*)d_in[2];
    const float* proj       = (const float*)d_in[3];
    float* out              = (float*)d_out;

    const int BL = in_sizes[1] / DDIM;

    static int configured = 0;
    if (!configured) {
        cudaFuncSetAttribute(attn_residual_kernel,
                             cudaFuncAttributeMaxDynamicSharedMemorySize,
                             SMEM_BYTES);
        configured = 1;
    }

    attn_residual_kernel<<<BL, THREADS, SMEM_BYTES>>>(blocks, partial,
                                                      norm_scale, proj,
                                                      out, BL);
}